// round 16
// baseline (speedup 1.0000x reference)
#include <cuda_runtime.h>
#include <cuda_fp16.h>

// ---------------- shared memory word offsets (fp32 indexing) ----------------
#define H_    0        // h tile 64x64 fp32, XOR swizzle (4096); hp16 aliases bytes 0..8192
#define HP_   4096     // hp tile 64x64 fp32, XOR swizzle (4096)
#define RG_   8192     // union: W [4096 floats] | p fp16 [4 heads x 2052 words]
#define PHW   2052
#define SV_   16416    // 256
#define DV_   16672    // 256
#define RED_  16928    // 512
#define DMX_  17440    // 16
#define MSK_  17456    // 64
#define MEAN_ 17520    // 64
#define RSTD_ 17584    // 64
#define INVP_ 17648    // 288
#define AV_   17936    // 256 (as0|ad0|as1|ad1)
#define BIA_  18192    // 80
#define SMF   18272    // 73088 bytes

#define L2E 1.4426950408889634f
#define HPSC 0.001953125f   // 1/512 fp16 scale for hp tile
typedef unsigned long long u64t;

__device__ __forceinline__ float ex2_(float x) {
    float r; asm("ex2.approx.f32 %0, %1;" : "=f"(r) : "f"(x)); return r;
}
__device__ __forceinline__ unsigned pk2(float a, float b) {
    __half2 t = __floats2half2_rn(a, b); return *(unsigned*)&t;
}
__device__ __forceinline__ u64t dup2(float x) {
    u64t r; unsigned u = __float_as_uint(x);
    asm("mov.b64 %0, {%1, %2};" : "=l"(r) : "r"(u), "r"(u));
    return r;
}
__device__ __forceinline__ u64t pkf2(float a, float b) {
    u64t r;
    asm("mov.b64 %0, {%1, %2};" : "=l"(r)
        : "r"(__float_as_uint(a)), "r"(__float_as_uint(b)));
    return r;
}
__device__ __forceinline__ u64t fma2(u64t a, u64t b, u64t c) {
    u64t d;
    asm("fma.rn.f32x2 %0, %1, %2, %3;" : "=l"(d) : "l"(a), "l"(b), "l"(c));
    return d;
}
__device__ __forceinline__ float2 upk2(u64t v) {
    unsigned lo, hi;
    asm("mov.b64 {%0, %1}, %2;" : "=r"(lo), "=r"(hi) : "l"(v));
    return make_float2(__uint_as_float(lo), __uint_as_float(hi));
}
__device__ __forceinline__ u64t h2f2(unsigned h) {
    __half2 hv = *(__half2*)&h;
    float2 f = __half22float2(hv);
    return pkf2(f.x, f.y);
}

// masked instance norm over XOR-swizzled fp32 h[64x64] (R13 verbatim)
__device__ __forceinline__ void inorm(float* __restrict__ sm, int tid) {
    int c = tid & 63, part = tid >> 6, n0 = part << 4;
    int chi = (c >> 2), clo = (c & 3);
    float s1 = 0.f, s2 = 0.f;
    #pragma unroll
    for (int k = 0; k < 16; k++) {
        int n = n0 + k;
        int ad = (n << 6) + (((chi ^ (n >> 2)) & 15) << 2) + clo;
        float v = sm[H_ + ad] * sm[MSK_ + n];
        s1 += v; s2 = fmaf(v, v, s2);
    }
    sm[RED_ + (part << 6) + c] = s1;
    sm[RED_ + 256 + (part << 6) + c] = s2;
    __syncthreads();
    if (tid < 64) {
        float cnt = 0.f;
        #pragma unroll 8
        for (int n = 0; n < 64; n++) cnt += sm[MSK_ + n];
        if (cnt <= 0.f) cnt = 1.f;
        float rc = 1.0f / cnt;
        float a = sm[RED_ + tid] + sm[RED_ + 64 + tid] + sm[RED_ + 128 + tid] + sm[RED_ + 192 + tid];
        float q = sm[RED_ + 256 + tid] + sm[RED_ + 320 + tid] + sm[RED_ + 384 + tid] + sm[RED_ + 448 + tid];
        float mn = a * rc;
        float var = fmaxf(q * rc - mn * mn, 0.f);
        sm[MEAN_ + tid] = mn;
        sm[RSTD_ + tid] = rsqrtf(var + 1e-5f);
    }
    __syncthreads();
    float mn = sm[MEAN_ + c], rs = sm[RSTD_ + c];
    #pragma unroll
    for (int k = 0; k < 16; k++) {
        int n = n0 + k;
        int ad = H_ + (n << 6) + (((chi ^ (n >> 2)) & 15) << 2) + clo;
        sm[ad] = (sm[ad] - mn) * rs;
    }
    __syncthreads();
}

// hp = h @ W; FFMA2 core (R13 verbatim, fp32 HP_ output only)
__device__ __forceinline__ void gemmW(float* __restrict__ sm, int tid) {
    int lane = tid & 31, w = tid >> 5;
    int nt = ((w >> 1) << 2) | (lane >> 3);
    int ct = ((w & 1) << 3) | (lane & 7);
    int n0 = nt << 2, c0 = ct << 2;
    u64t A0l = 0, A0h = 0, A1l = 0, A1h = 0, A2l = 0, A2h = 0, A3l = 0, A3h = 0;
    #pragma unroll
    for (int fb = 0; fb < 16; fb++) {
        int uo = ((fb ^ nt) & 15) << 2;
        const char* wb = (const char*)&sm[RG_ + (fb << 8) + c0];
        ulonglong2 b0 = *(const ulonglong2*)(wb);
        ulonglong2 b1 = *(const ulonglong2*)(wb + 256);
        ulonglong2 b2 = *(const ulonglong2*)(wb + 512);
        ulonglong2 b3 = *(const ulonglong2*)(wb + 768);
        float4 a; u64t s;
        a = *(const float4*)&sm[H_ + ((n0 + 0) << 6) + uo];
        s = dup2(a.x); A0l = fma2(s, b0.x, A0l); A0h = fma2(s, b0.y, A0h);
        s = dup2(a.y); A0l = fma2(s, b1.x, A0l); A0h = fma2(s, b1.y, A0h);
        s = dup2(a.z); A0l = fma2(s, b2.x, A0l); A0h = fma2(s, b2.y, A0h);
        s = dup2(a.w); A0l = fma2(s, b3.x, A0l); A0h = fma2(s, b3.y, A0h);
        a = *(const float4*)&sm[H_ + ((n0 + 1) << 6) + uo];
        s = dup2(a.x); A1l = fma2(s, b0.x, A1l); A1h = fma2(s, b0.y, A1h);
        s = dup2(a.y); A1l = fma2(s, b1.x, A1l); A1h = fma2(s, b1.y, A1h);
        s = dup2(a.z); A1l = fma2(s, b2.x, A1l); A1h = fma2(s, b2.y, A1h);
        s = dup2(a.w); A1l = fma2(s, b3.x, A1l); A1h = fma2(s, b3.y, A1h);
        a = *(const float4*)&sm[H_ + ((n0 + 2) << 6) + uo];
        s = dup2(a.x); A2l = fma2(s, b0.x, A2l); A2h = fma2(s, b0.y, A2h);
        s = dup2(a.y); A2l = fma2(s, b1.x, A2l); A2h = fma2(s, b1.y, A2h);
        s = dup2(a.z); A2l = fma2(s, b2.x, A2l); A2h = fma2(s, b2.y, A2h);
        s = dup2(a.w); A2l = fma2(s, b3.x, A2l); A2h = fma2(s, b3.y, A2h);
        a = *(const float4*)&sm[H_ + ((n0 + 3) << 6) + uo];
        s = dup2(a.x); A3l = fma2(s, b0.x, A3l); A3h = fma2(s, b0.y, A3h);
        s = dup2(a.y); A3l = fma2(s, b1.x, A3l); A3h = fma2(s, b1.y, A3h);
        s = dup2(a.z); A3l = fma2(s, b2.x, A3l); A3h = fma2(s, b2.y, A3h);
        s = dup2(a.w); A3l = fma2(s, b3.x, A3l); A3h = fma2(s, b3.y, A3h);
    }
    int so = ((ct ^ nt) & 15) << 2;
    ulonglong2 st;
    st.x = A0l; st.y = A0h; *(ulonglong2*)&sm[HP_ + ((n0 + 0) << 6) + so] = st;
    st.x = A1l; st.y = A1h; *(ulonglong2*)&sm[HP_ + ((n0 + 1) << 6) + so] = st;
    st.x = A2l; st.y = A2h; *(ulonglong2*)&sm[HP_ + ((n0 + 2) << 6) + so] = st;
    st.x = A3l; st.y = A3h; *(ulonglong2*)&sm[HP_ + ((n0 + 3) << 6) + so] = st;
}

// out = (p_fp16 @ hp16) * (512/psum) + bias [+ ELU]; hp16 = hp/512 plain 128B rows at H_
__device__ __forceinline__ void aggregate(float* __restrict__ sm,
                                          const unsigned* __restrict__ smu,
                                          int tid, int layer,
                                          float* __restrict__ gout) {
    int lane = tid & 31, w = tid >> 5;
    int nt = ((w >> 1) << 2) | (lane >> 3);
    int ct = ((w & 1) << 3) | (lane & 7);
    int n0 = nt << 2, c0 = ct << 2;
    int head = (layer == 0) ? (ct >> 2) : 0;
    int swm = (layer == 0) ? 15 : 12;
    const unsigned* A = smu + RG_ + head * PHW;
    const char* hbase = (const char*)sm + ct * 8;     // hp16 at H_ bytes 0..8192
    u64t acl[4] = {0, 0, 0, 0}, ach[4] = {0, 0, 0, 0};
    #pragma unroll
    for (int fb = 0; fb < 16; fb++) {
        const char* hb = hbase + (fb << 9);           // row 4fb * 128 bytes
        uint2 q0 = *(const uint2*)(hb);
        uint2 q1 = *(const uint2*)(hb + 128);
        uint2 q2 = *(const uint2*)(hb + 256);
        uint2 q3 = *(const uint2*)(hb + 384);
        u64t b0x = h2f2(q0.x), b0y = h2f2(q0.y);
        u64t b1x = h2f2(q1.x), b1y = h2f2(q1.y);
        u64t b2x = h2f2(q2.x), b2y = h2f2(q2.y);
        u64t b3x = h2f2(q3.x), b3y = h2f2(q3.y);
        #pragma unroll
        for (int r = 0; r < 4; r++) {
            int n = n0 + r;
            uint2 av = *(const uint2*)(A + (n << 5) + (((fb ^ (n & swm)) & 15) << 1));
            float2 f01 = __half22float2(*(__half2*)&av.x);
            float2 f23 = __half22float2(*(__half2*)&av.y);
            u64t s;
            s = dup2(f01.x); acl[r] = fma2(s, b0x, acl[r]); ach[r] = fma2(s, b0y, ach[r]);
            s = dup2(f01.y); acl[r] = fma2(s, b1x, acl[r]); ach[r] = fma2(s, b1y, ach[r]);
            s = dup2(f23.x); acl[r] = fma2(s, b2x, acl[r]); ach[r] = fma2(s, b2y, ach[r]);
            s = dup2(f23.y); acl[r] = fma2(s, b3x, acl[r]); ach[r] = fma2(s, b3y, ach[r]);
        }
    }
    if (layer == 0) {
        __syncthreads();   // all hp16/p reads done before epilogue overwrites H_
        float4 bias = *(const float4*)&sm[BIA_ + ((ct & 3) << 2)];
        int so = ((ct ^ nt) & 15) << 2;
        #pragma unroll
        for (int r = 0; r < 4; r++) {
            float iv = sm[INVP_ + head * 68 + n0 + r];   // = 512/psum
            float2 lo = upk2(acl[r]), hi = upk2(ach[r]);
            float4 e;
            e.x = fmaf(lo.x, iv, bias.x);
            e.y = fmaf(lo.y, iv, bias.y);
            e.z = fmaf(hi.x, iv, bias.z);
            e.w = fmaf(hi.y, iv, bias.w);
            e.x = (e.x > 0.f) ? e.x : (ex2_(e.x * L2E) - 1.0f);
            e.y = (e.y > 0.f) ? e.y : (ex2_(e.y * L2E) - 1.0f);
            e.z = (e.z > 0.f) ? e.z : (ex2_(e.z * L2E) - 1.0f);
            e.w = (e.w > 0.f) ? e.w : (ex2_(e.w * L2E) - 1.0f);
            *(float4*)&sm[H_ + ((n0 + r) << 6) + so] = e;
        }
    } else {
        float4 bias = *(const float4*)&sm[BIA_ + 16 + c0];
        #pragma unroll
        for (int r = 0; r < 4; r++) {
            float iv = sm[INVP_ + n0 + r];               // = 512/psum
            float2 lo = upk2(acl[r]), hi = upk2(ach[r]);
            float4 e;
            e.x = fmaf(lo.x, iv, bias.x);
            e.y = fmaf(lo.y, iv, bias.y);
            e.z = fmaf(hi.x, iv, bias.z);
            e.w = fmaf(hi.y, iv, bias.w);
            *(float4*)&gout[((n0 + r) << 6) + c0] = e;
        }
    }
}

__global__ __launch_bounds__(256, 3)
void gat_kernel(const float* __restrict__ x,
                const int* __restrict__ fhi,
                const float* __restrict__ w0,
                const float* __restrict__ as0,
                const float* __restrict__ ad0,
                const float* __restrict__ b0,
                const float* __restrict__ w1,
                const float* __restrict__ as1,
                const float* __restrict__ ad1,
                const float* __restrict__ b1,
                float* __restrict__ out) {
    extern __shared__ float sm[];
    unsigned* smu = (unsigned*)sm;
    int b = blockIdx.x;
    int scene = b >> 3, t = b & 7;
    int tid = threadIdx.x;
    int lane = tid & 31;

    // ---- global loads (R13 verbatim) ----
    {
        const float4* xb = (const float4*)(x + (size_t)b * 4096);
        #pragma unroll
        for (int k = 0; k < 4; k++) {
            int i = tid + (k << 8);
            int n = i >> 4, chunk = i & 15;
            *(float4*)&sm[H_ + (n << 6) + (((chunk ^ (n >> 2)) & 15) << 2)] = xb[i];
        }
        if (tid < 64) {
            sm[MSK_ + tid] = (fhi[(scene << 6) + tid] <= t) ? 1.0f : 0.0f;
            sm[AV_ + tid]       = as0[tid];
            sm[AV_ + 64 + tid]  = ad0[tid];
            sm[AV_ + 128 + tid] = as1[tid];
            sm[AV_ + 192 + tid] = ad1[tid];
            sm[BIA_ + 16 + tid] = b1[tid];
            if (tid < 16) sm[BIA_ + tid] = b0[tid];
        }
        #pragma unroll
        for (int k = 0; k < 16; k++) {
            int i = tid + (k << 8);
            int f = i >> 6, c = i & 63;
            sm[RG_ + i] = w0[((c >> 4) << 10) + (f << 4) + (c & 15)];
        }
    }
    __syncthreads();

    // ================= layer 0 =================
    inorm(sm, tid);
    gemmW(sm, tid);
    __syncthreads();

    { // convert HP_ fp32 -> hp16 (hp/512) at H_ (plain 128B rows); column-parallel
        int c = tid & 63, part = tid >> 6, n0c = part << 4;
        int chi = c >> 2, clo = c & 3;
        char* hb = (char*)sm;
        #pragma unroll
        for (int k = 0; k < 16; k++) {
            int n = n0c + k;
            float v = sm[HP_ + (n << 6) + (((chi ^ (n >> 2)) & 15) << 2) + clo];
            *(__half*)(hb + n * 128 + c * 2) = __float2half_rn(v * HPSC);
        }
    }
    { // scores (R13 verbatim): s,d per (head, node); DV masked; per-warp max
        int hh = tid >> 6, n = tid & 63, a = n >> 2;
        float s = 0.f, d = 0.f;
        #pragma unroll
        for (int j = 0; j < 4; j++) {
            int jj = (j + n) & 3;
            int chunk = (hh << 2) + jj;
            float4 v = *(const float4*)&sm[HP_ + (n << 6) + (((chunk ^ a) & 15) << 2)];
            float4 vs = *(const float4*)&sm[AV_ + (hh << 4) + (jj << 2)];
            float4 vd = *(const float4*)&sm[AV_ + 64 + (hh << 4) + (jj << 2)];
            s = fmaf(v.x, vs.x, fmaf(v.y, vs.y, fmaf(v.z, vs.z, fmaf(v.w, vs.w, s))));
            d = fmaf(v.x, vd.x, fmaf(v.y, vd.y, fmaf(v.z, vd.z, fmaf(v.w, vd.w, d))));
        }
        sm[SV_ + tid] = s;
        float dm = (sm[MSK_ + n] > 0.f) ? d : -3.0e38f;
        sm[DV_ + tid] = dm;
        float md = dm;
        #pragma unroll
        for (int off = 16; off > 0; off >>= 1)
            md = fmaxf(md, __shfl_xor_sync(0xffffffffu, md, off));
        if (lane == 0) sm[DMX_ + (tid >> 5)] = md;
    }
    __syncthreads();

    { // p-pass L0 (R13 verbatim except INVP scale)
        int hh = tid >> 6, n = tid & 63;
        float sB = sm[SV_ + tid];
        float valid = sm[MSK_ + n];
        float dmx = fmaxf(sm[DMX_ + (hh << 1)], sm[DMX_ + (hh << 1) + 1]);
        float mxv = sB + dmx; mxv = fmaxf(mxv, 0.2f * mxv);
        float nml = -mxv * L2E;
        float psum = 0.f;
        unsigned* pb = smu + RG_ + hh * PHW + (n << 5);
        int nx = n & 15;
        const float* dvb = &sm[DV_ + (hh << 6)];
        #pragma unroll 4
        for (int c = 0; c < 16; c++) {
            float4 d4 = *(const float4*)&dvb[c << 2];
            float v, lr;
            float4 pv;
            v = sB + d4.x; lr = fmaxf(v, 0.2f * v); pv.x = ex2_(fmaf(lr, L2E, nml));
            v = sB + d4.y; lr = fmaxf(v, 0.2f * v); pv.y = ex2_(fmaf(lr, L2E, nml));
            v = sB + d4.z; lr = fmaxf(v, 0.2f * v); pv.z = ex2_(fmaf(lr, L2E, nml));
            v = sB + d4.w; lr = fmaxf(v, 0.2f * v); pv.w = ex2_(fmaf(lr, L2E, nml));
            if (valid <= 0.f) { pv.x = 1.f; pv.y = 1.f; pv.z = 1.f; pv.w = 1.f; }
            psum += (pv.x + pv.y) + (pv.z + pv.w);
            uint2 uu; uu.x = pk2(pv.x, pv.y); uu.y = pk2(pv.z, pv.w);
            *(uint2*)(pb + ((c ^ nx) << 1)) = uu;
        }
        sm[INVP_ + hh * 68 + n] = 512.0f / psum;
    }
    __syncthreads();

    aggregate(sm, smu, tid, 0, (float*)0);   // internal sync; ELU(out0)+b0 -> H_
    __syncthreads();

    // load W1 (overwrites dead p region)
    #pragma unroll
    for (int k = 0; k < 16; k++) {
        int i = tid + (k << 8);
        sm[RG_ + i] = w1[i];
    }
    __syncthreads();

    // ================= layer 1 =================
    inorm(sm, tid);
    gemmW(sm, tid);
    __syncthreads();

    { // convert HP_ -> hp16 at H_ (h_L1 dead)
        int c = tid & 63, part = tid >> 6, n0c = part << 4;
        int chi = c >> 2, clo = c & 3;
        char* hb = (char*)sm;
        #pragma unroll
        for (int k = 0; k < 16; k++) {
            int n = n0c + k;
            float v = sm[HP_ + (n << 6) + (((chi ^ (n >> 2)) & 15) << 2) + clo];
            *(__half*)(hb + n * 128 + c * 2) = __float2half_rn(v * HPSC);
        }
    }
    { // scores L1 (R13 verbatim): seg-split partial dots
        int row = tid & 63, seg = tid >> 6, a = row >> 2;
        float s = 0.f, d = 0.f;
        #pragma unroll
        for (int j = 0; j < 4; j++) {
            int jj = (j + row) & 3;
            int chunk = (seg << 2) + jj;
            float4 v = *(const float4*)&sm[HP_ + (row << 6) + (((chunk ^ a) & 15) << 2)];
            float4 vs = *(const float4*)&sm[AV_ + 128 + (seg << 4) + (jj << 2)];
            float4 vd = *(const float4*)&sm[AV_ + 192 + (seg << 4) + (jj << 2)];
            s = fmaf(v.x, vs.x, fmaf(v.y, vs.y, fmaf(v.z, vs.z, fmaf(v.w, vs.w, s))));
            d = fmaf(v.x, vd.x, fmaf(v.y, vd.y, fmaf(v.z, vd.z, fmaf(v.w, vd.w, d))));
        }
        sm[RED_ + tid] = s;
        sm[RED_ + 256 + tid] = d;
    }
    __syncthreads();
    if (tid < 64) {
        float s = sm[RED_ + tid] + sm[RED_ + 64 + tid] + sm[RED_ + 128 + tid] + sm[RED_ + 192 + tid];
        float d = sm[RED_ + 256 + tid] + sm[RED_ + 320 + tid] + sm[RED_ + 384 + tid] + sm[RED_ + 448 + tid];
        sm[SV_ + tid] = s;
        float dm = (sm[MSK_ + tid] > 0.f) ? d : -3.0e38f;
        sm[DV_ + tid] = dm;
        float md = dm;
        #pragma unroll
        for (int off = 16; off > 0; off >>= 1)
            md = fmaxf(md, __shfl_xor_sync(0xffffffffu, md, off));
        if (lane == 0) sm[DMX_ + 8 + (tid >> 5)] = md;
    }
    __syncthreads();

    { // p-pass L1 (R13 verbatim)
        int row = tid & 63, seg = tid >> 6;
        float sB = sm[SV_ + row];
        float valid = sm[MSK_ + row];
        float dmx = fmaxf(sm[DMX_ + 8], sm[DMX_ + 9]);
        float mxv = sB + dmx; mxv = fmaxf(mxv, 0.2f * mxv);
        float nml = -mxv * L2E;
        float psum = 0.f;
        unsigned* pb = smu + RG_ + (row << 5);
        int nx = row & 12;
        #pragma unroll
        for (int i = 0; i < 4; i++) {
            int jj = (i + row) & 3;
            int sg = (seg << 2) + jj;
            float4 d4 = *(const float4*)&sm[DV_ + (sg << 2)];
            float v, lr;
            float4 pv;
            v = sB + d4.x; lr = fmaxf(v, 0.2f * v); pv.x = ex2_(fmaf(lr, L2E, nml));
            v = sB + d4.y; lr = fmaxf(v, 0.2f * v); pv.y = ex2_(fmaf(lr, L2E, nml));
            v = sB + d4.z; lr = fmaxf(v, 0.2f * v); pv.z = ex2_(fmaf(lr, L2E, nml));
            v = sB + d4.w; lr = fmaxf(v, 0.2f * v); pv.w = ex2_(fmaf(lr, L2E, nml));
            if (valid <= 0.f) { pv.x = 1.f; pv.y = 1.f; pv.z = 1.f; pv.w = 1.f; }
            psum += (pv.x + pv.y) + (pv.z + pv.w);
            uint2 uu; uu.x = pk2(pv.x, pv.y); uu.y = pk2(pv.z, pv.w);
            *(uint2*)(pb + (((sg ^ nx) & 15) << 1)) = uu;
        }
        sm[RED_ + tid] = psum;
    }
    __syncthreads();
    if (tid < 64)
        sm[INVP_ + tid] = 512.0f / (sm[RED_ + tid] + sm[RED_ + 64 + tid] +
                                    sm[RED_ + 128 + tid] + sm[RED_ + 192 + tid]);
    __syncthreads();

    aggregate(sm, smu, tid, 1, out + (size_t)b * 4096);
}

extern "C" void kernel_launch(void* const* d_in, const int* in_sizes, int n_in,
                              void* d_out, int out_size) {
    const float* x   = (const float*)d_in[0];
    const int*   fhi = (const int*)d_in[1];
    const float* w0  = (const float*)d_in[2];
    const float* as0 = (const float*)d_in[3];
    const float* ad0 = (const float*)d_in[4];
    const float* b0  = (const float*)d_in[5];
    const float* w1  = (const float*)d_in[6];
    const float* as1 = (const float*)d_in[7];
    const float* ad1 = (const float*)d_in[8];
    const float* b1  = (const float*)d_in[9];
    float* out = (float*)d_out;

    const int smem = SMF * 4;   // 73088 bytes
    cudaFuncSetAttribute(gat_kernel, cudaFuncAttributeMaxDynamicSharedMemorySize, smem);
    gat_kernel<<<8192, 256, smem>>>(x, fhi, w0, as0, ad0, b0, w1, as1, ad1, b1, out);
}

// round 17
// speedup vs baseline: 1.0378x; 1.0378x over previous
#include <cuda_runtime.h>
#include <cuda_fp16.h>

// ---------------- shared memory word offsets (fp32 indexing) ----------------
#define H_    0        // h fp32 XOR swizzle (4096 w); hp16 (hp/512, plain 128B rows)
                       // aliases bytes 0..8191 after each gemm
#define RG_   4096     // union: W fp32 [4096 w] | p fp16 [4 heads x 2052 w]
#define PHW   2052
#define SV_   12320    // 256
#define DV_   12576    // 256
#define RED_  12832    // 512
#define DMX_  13344    // 16
#define MSK_  13360    // 64
#define MEAN_ 13424    // 64
#define RSTD_ 13488    // 64
#define INVP_ 13552    // 288
#define AV_   13840    // 256 (as0|ad0|as1|ad1)
#define BIA_  14096    // 80
#define SMW   14176    // 56704 bytes

#define L2E 1.4426950408889634f
#define HPSC 0.001953125f   // 1/512 fp16 scale for hp tile
typedef unsigned long long u64t;

__device__ __forceinline__ float ex2_(float x) {
    float r; asm("ex2.approx.f32 %0, %1;" : "=f"(r) : "f"(x)); return r;
}
__device__ __forceinline__ unsigned pk2(float a, float b) {
    __half2 t = __floats2half2_rn(a, b); return *(unsigned*)&t;
}
__device__ __forceinline__ u64t dup2(float x) {
    u64t r; unsigned u = __float_as_uint(x);
    asm("mov.b64 %0, {%1, %2};" : "=l"(r) : "r"(u), "r"(u));
    return r;
}
__device__ __forceinline__ u64t pkf2(float a, float b) {
    u64t r;
    asm("mov.b64 %0, {%1, %2};" : "=l"(r)
        : "r"(__float_as_uint(a)), "r"(__float_as_uint(b)));
    return r;
}
__device__ __forceinline__ u64t fma2(u64t a, u64t b, u64t c) {
    u64t d;
    asm("fma.rn.f32x2 %0, %1, %2, %3;" : "=l"(d) : "l"(a), "l"(b), "l"(c));
    return d;
}
__device__ __forceinline__ float2 upk2(u64t v) {
    unsigned lo, hi;
    asm("mov.b64 {%0, %1}, %2;" : "=r"(lo), "=r"(hi) : "l"(v));
    return make_float2(__uint_as_float(lo), __uint_as_float(hi));
}
__device__ __forceinline__ u64t h2f2(unsigned h) {
    __half2 hv = *(__half2*)&h;
    float2 f = __half22float2(hv);
    return pkf2(f.x, f.y);
}

// masked instance norm over XOR-swizzled fp32 h[64x64] (proven verbatim)
__device__ __forceinline__ void inorm(float* __restrict__ sm, int tid) {
    int c = tid & 63, part = tid >> 6, n0 = part << 4;
    int chi = (c >> 2), clo = (c & 3);
    float s1 = 0.f, s2 = 0.f;
    #pragma unroll
    for (int k = 0; k < 16; k++) {
        int n = n0 + k;
        int ad = (n << 6) + (((chi ^ (n >> 2)) & 15) << 2) + clo;
        float v = sm[H_ + ad] * sm[MSK_ + n];
        s1 += v; s2 = fmaf(v, v, s2);
    }
    sm[RED_ + (part << 6) + c] = s1;
    sm[RED_ + 256 + (part << 6) + c] = s2;
    __syncthreads();
    if (tid < 64) {
        float cnt = 0.f;
        #pragma unroll 8
        for (int n = 0; n < 64; n++) cnt += sm[MSK_ + n];
        if (cnt <= 0.f) cnt = 1.f;
        float rc = 1.0f / cnt;
        float a = sm[RED_ + tid] + sm[RED_ + 64 + tid] + sm[RED_ + 128 + tid] + sm[RED_ + 192 + tid];
        float q = sm[RED_ + 256 + tid] + sm[RED_ + 320 + tid] + sm[RED_ + 384 + tid] + sm[RED_ + 448 + tid];
        float mn = a * rc;
        float var = fmaxf(q * rc - mn * mn, 0.f);
        sm[MEAN_ + tid] = mn;
        sm[RSTD_ + tid] = rsqrtf(var + 1e-5f);
    }
    __syncthreads();
    float mn = sm[MEAN_ + c], rs = sm[RSTD_ + c];
    #pragma unroll
    for (int k = 0; k < 16; k++) {
        int n = n0 + k;
        int ad = H_ + (n << 6) + (((chi ^ (n >> 2)) & 15) << 2) + clo;
        sm[ad] = (sm[ad] - mn) * rs;
    }
    __syncthreads();
}

// hp = h @ W (FFMA2 core). Epilogue: s/d score partials from fp32 accumulators
// (shfl-reduced), hp/512 -> fp16 plain tile at H_ (after sync; h is dead).
__device__ __forceinline__ void gemmW_ep(float* __restrict__ sm, int tid, int layer) {
    int lane = tid & 31, w = tid >> 5;
    int nt = ((w >> 1) << 2) | (lane >> 3);
    int ct = ((w & 1) << 3) | (lane & 7);
    int n0 = nt << 2, c0 = ct << 2;
    u64t A0l = 0, A0h = 0, A1l = 0, A1h = 0, A2l = 0, A2h = 0, A3l = 0, A3h = 0;
    #pragma unroll
    for (int fb = 0; fb < 16; fb++) {
        int uo = ((fb ^ nt) & 15) << 2;
        const char* wb = (const char*)&sm[RG_ + (fb << 8) + c0];
        ulonglong2 b0 = *(const ulonglong2*)(wb);
        ulonglong2 b1 = *(const ulonglong2*)(wb + 256);
        ulonglong2 b2 = *(const ulonglong2*)(wb + 512);
        ulonglong2 b3 = *(const ulonglong2*)(wb + 768);
        float4 a; u64t s;
        a = *(const float4*)&sm[H_ + ((n0 + 0) << 6) + uo];
        s = dup2(a.x); A0l = fma2(s, b0.x, A0l); A0h = fma2(s, b0.y, A0h);
        s = dup2(a.y); A0l = fma2(s, b1.x, A0l); A0h = fma2(s, b1.y, A0h);
        s = dup2(a.z); A0l = fma2(s, b2.x, A0l); A0h = fma2(s, b2.y, A0h);
        s = dup2(a.w); A0l = fma2(s, b3.x, A0l); A0h = fma2(s, b3.y, A0h);
        a = *(const float4*)&sm[H_ + ((n0 + 1) << 6) + uo];
        s = dup2(a.x); A1l = fma2(s, b0.x, A1l); A1h = fma2(s, b0.y, A1h);
        s = dup2(a.y); A1l = fma2(s, b1.x, A1l); A1h = fma2(s, b1.y, A1h);
        s = dup2(a.z); A1l = fma2(s, b2.x, A1l); A1h = fma2(s, b2.y, A1h);
        s = dup2(a.w); A1l = fma2(s, b3.x, A1l); A1h = fma2(s, b3.y, A1h);
        a = *(const float4*)&sm[H_ + ((n0 + 2) << 6) + uo];
        s = dup2(a.x); A2l = fma2(s, b0.x, A2l); A2h = fma2(s, b0.y, A2h);
        s = dup2(a.y); A2l = fma2(s, b1.x, A2l); A2h = fma2(s, b1.y, A2h);
        s = dup2(a.z); A2l = fma2(s, b2.x, A2l); A2h = fma2(s, b2.y, A2h);
        s = dup2(a.w); A2l = fma2(s, b3.x, A2l); A2h = fma2(s, b3.y, A2h);
        a = *(const float4*)&sm[H_ + ((n0 + 3) << 6) + uo];
        s = dup2(a.x); A3l = fma2(s, b0.x, A3l); A3h = fma2(s, b0.y, A3h);
        s = dup2(a.y); A3l = fma2(s, b1.x, A3l); A3h = fma2(s, b1.y, A3h);
        s = dup2(a.z); A3l = fma2(s, b2.x, A3l); A3h = fma2(s, b2.y, A3h);
        s = dup2(a.w); A3l = fma2(s, b3.x, A3l); A3h = fma2(s, b3.y, A3h);
    }
    // ---- scores from fp32 accumulators (exact logits) ----
    int avs = (layer == 0) ? (AV_ + ((ct >> 2) << 4) + ((ct & 3) << 2))
                           : (AV_ + 128 + c0);
    float4 va  = *(const float4*)&sm[avs];
    float4 vd4 = *(const float4*)&sm[avs + 64];
    float2 l0 = upk2(A0l), h0 = upk2(A0h);
    float2 l1 = upk2(A1l), h1 = upk2(A1h);
    float2 l2 = upk2(A2l), h2 = upk2(A2h);
    float2 l3 = upk2(A3l), h3 = upk2(A3h);
    float sp[4], dp[4];
    sp[0] = fmaf(l0.x, va.x, fmaf(l0.y, va.y, fmaf(h0.x, va.z, h0.y * va.w)));
    dp[0] = fmaf(l0.x, vd4.x, fmaf(l0.y, vd4.y, fmaf(h0.x, vd4.z, h0.y * vd4.w)));
    sp[1] = fmaf(l1.x, va.x, fmaf(l1.y, va.y, fmaf(h1.x, va.z, h1.y * va.w)));
    dp[1] = fmaf(l1.x, vd4.x, fmaf(l1.y, vd4.y, fmaf(h1.x, vd4.z, h1.y * vd4.w)));
    sp[2] = fmaf(l2.x, va.x, fmaf(l2.y, va.y, fmaf(h2.x, va.z, h2.y * va.w)));
    dp[2] = fmaf(l2.x, vd4.x, fmaf(l2.y, vd4.y, fmaf(h2.x, vd4.z, h2.y * vd4.w)));
    sp[3] = fmaf(l3.x, va.x, fmaf(l3.y, va.y, fmaf(h3.x, va.z, h3.y * va.w)));
    dp[3] = fmaf(l3.x, vd4.x, fmaf(l3.y, vd4.y, fmaf(h3.x, vd4.z, h3.y * vd4.w)));
    __syncthreads();   // all main-loop reads of H_ done before hp16 overwrites it
    // ---- hp16 = hp/512, plain 128B rows at H_ ----
    char* hb = (char*)sm + n0 * 128 + (ct << 3);
    uint2 st;
    st.x = pk2(l0.x * HPSC, l0.y * HPSC); st.y = pk2(h0.x * HPSC, h0.y * HPSC);
    *(uint2*)(hb) = st;
    st.x = pk2(l1.x * HPSC, l1.y * HPSC); st.y = pk2(h1.x * HPSC, h1.y * HPSC);
    *(uint2*)(hb + 128) = st;
    st.x = pk2(l2.x * HPSC, l2.y * HPSC); st.y = pk2(h2.x * HPSC, h2.y * HPSC);
    *(uint2*)(hb + 256) = st;
    st.x = pk2(l3.x * HPSC, l3.y * HPSC); st.y = pk2(h3.x * HPSC, h3.y * HPSC);
    *(uint2*)(hb + 384) = st;
    // ---- reduce score partials ----
    if (layer == 0) {
        #pragma unroll
        for (int off = 1; off <= 2; off <<= 1) {
            #pragma unroll
            for (int r = 0; r < 4; r++) {
                sp[r] += __shfl_xor_sync(0xffffffffu, sp[r], off);
                dp[r] += __shfl_xor_sync(0xffffffffu, dp[r], off);
            }
        }
        if ((lane & 3) == 0) {
            int hh = ct >> 2;
            #pragma unroll
            for (int r = 0; r < 4; r++) {
                sm[SV_ + (hh << 6) + n0 + r] = sp[r];
                sm[DV_ + (hh << 6) + n0 + r] = dp[r];   // raw d; masked later
            }
        }
    } else {
        #pragma unroll
        for (int off = 1; off <= 4; off <<= 1) {
            #pragma unroll
            for (int r = 0; r < 4; r++) {
                sp[r] += __shfl_xor_sync(0xffffffffu, sp[r], off);
                dp[r] += __shfl_xor_sync(0xffffffffu, dp[r], off);
            }
        }
        if ((lane & 7) == 0) {
            int half = w & 1;
            #pragma unroll
            for (int r = 0; r < 4; r++) {
                sm[RED_ + (half << 6) + n0 + r] = sp[r];
                sm[RED_ + 128 + (half << 6) + n0 + r] = dp[r];
            }
        }
    }
}

// out = (p_fp16 @ hp16) * (512/psum) + bias [+ ELU]; hp16 plain rows at H_
__device__ __forceinline__ void aggregate(float* __restrict__ sm,
                                          const unsigned* __restrict__ smu,
                                          int tid, int layer,
                                          float* __restrict__ gout) {
    int lane = tid & 31, w = tid >> 5;
    int nt = ((w >> 1) << 2) | (lane >> 3);
    int ct = ((w & 1) << 3) | (lane & 7);
    int n0 = nt << 2, c0 = ct << 2;
    int head = (layer == 0) ? (ct >> 2) : 0;
    int swm = (layer == 0) ? 15 : 12;
    const unsigned* A = smu + RG_ + head * PHW;
    const char* hbase = (const char*)sm + (ct << 3);
    u64t acl[4] = {0, 0, 0, 0}, ach[4] = {0, 0, 0, 0};
    #pragma unroll
    for (int fb = 0; fb < 16; fb++) {
        const char* hb = hbase + (fb << 9);
        uint2 q0 = *(const uint2*)(hb);
        uint2 q1 = *(const uint2*)(hb + 128);
        uint2 q2 = *(const uint2*)(hb + 256);
        uint2 q3 = *(const uint2*)(hb + 384);
        u64t b0x = h2f2(q0.x), b0y = h2f2(q0.y);
        u64t b1x = h2f2(q1.x), b1y = h2f2(q1.y);
        u64t b2x = h2f2(q2.x), b2y = h2f2(q2.y);
        u64t b3x = h2f2(q3.x), b3y = h2f2(q3.y);
        #pragma unroll
        for (int r = 0; r < 4; r++) {
            int n = n0 + r;
            uint2 av = *(const uint2*)(A + (n << 5) + (((fb ^ (n & swm)) & 15) << 1));
            float2 f01 = __half22float2(*(__half2*)&av.x);
            float2 f23 = __half22float2(*(__half2*)&av.y);
            u64t s;
            s = dup2(f01.x); acl[r] = fma2(s, b0x, acl[r]); ach[r] = fma2(s, b0y, ach[r]);
            s = dup2(f01.y); acl[r] = fma2(s, b1x, acl[r]); ach[r] = fma2(s, b1y, ach[r]);
            s = dup2(f23.x); acl[r] = fma2(s, b2x, acl[r]); ach[r] = fma2(s, b2y, ach[r]);
            s = dup2(f23.y); acl[r] = fma2(s, b3x, acl[r]); ach[r] = fma2(s, b3y, ach[r]);
        }
    }
    if (layer == 0) {
        __syncthreads();   // all hp16/p reads done before epilogue overwrites H_
        float4 bias = *(const float4*)&sm[BIA_ + ((ct & 3) << 2)];
        int so = ((ct ^ nt) & 15) << 2;
        #pragma unroll
        for (int r = 0; r < 4; r++) {
            float iv = sm[INVP_ + head * 68 + n0 + r];   // = 512/psum
            float2 lo = upk2(acl[r]), hi = upk2(ach[r]);
            float4 e;
            e.x = fmaf(lo.x, iv, bias.x);
            e.y = fmaf(lo.y, iv, bias.y);
            e.z = fmaf(hi.x, iv, bias.z);
            e.w = fmaf(hi.y, iv, bias.w);
            e.x = (e.x > 0.f) ? e.x : (ex2_(e.x * L2E) - 1.0f);
            e.y = (e.y > 0.f) ? e.y : (ex2_(e.y * L2E) - 1.0f);
            e.z = (e.z > 0.f) ? e.z : (ex2_(e.z * L2E) - 1.0f);
            e.w = (e.w > 0.f) ? e.w : (ex2_(e.w * L2E) - 1.0f);
            *(float4*)&sm[H_ + ((n0 + r) << 6) + so] = e;
        }
    } else {
        float4 bias = *(const float4*)&sm[BIA_ + 16 + c0];
        #pragma unroll
        for (int r = 0; r < 4; r++) {
            float iv = sm[INVP_ + n0 + r];               // = 512/psum
            float2 lo = upk2(acl[r]), hi = upk2(ach[r]);
            float4 e;
            e.x = fmaf(lo.x, iv, bias.x);
            e.y = fmaf(lo.y, iv, bias.y);
            e.z = fmaf(hi.x, iv, bias.z);
            e.w = fmaf(hi.y, iv, bias.w);
            *(float4*)&gout[((n0 + r) << 6) + c0] = e;
        }
    }
}

__global__ __launch_bounds__(256, 4)
void gat_kernel(const float* __restrict__ x,
                const int* __restrict__ fhi,
                const float* __restrict__ w0,
                const float* __restrict__ as0,
                const float* __restrict__ ad0,
                const float* __restrict__ b0,
                const float* __restrict__ w1,
                const float* __restrict__ as1,
                const float* __restrict__ ad1,
                const float* __restrict__ b1,
                float* __restrict__ out) {
    extern __shared__ float sm[];
    unsigned* smu = (unsigned*)sm;
    int b = blockIdx.x;
    int scene = b >> 3, t = b & 7;
    int tid = threadIdx.x;
    int lane = tid & 31;

    // ---- global loads ----
    {
        const float4* xb = (const float4*)(x + (size_t)b * 4096);
        #pragma unroll
        for (int k = 0; k < 4; k++) {
            int i = tid + (k << 8);
            int n = i >> 4, chunk = i & 15;
            *(float4*)&sm[H_ + (n << 6) + (((chunk ^ (n >> 2)) & 15) << 2)] = xb[i];
        }
        if (tid < 64) {
            sm[MSK_ + tid] = (fhi[(scene << 6) + tid] <= t) ? 1.0f : 0.0f;
            sm[AV_ + tid]       = as0[tid];
            sm[AV_ + 64 + tid]  = ad0[tid];
            sm[AV_ + 128 + tid] = as1[tid];
            sm[AV_ + 192 + tid] = ad1[tid];
            sm[BIA_ + 16 + tid] = b1[tid];
            if (tid < 16) sm[BIA_ + tid] = b0[tid];
        }
        #pragma unroll
        for (int k = 0; k < 16; k++) {
            int i = tid + (k << 8);
            int f = i >> 6, c = i & 63;
            sm[RG_ + i] = w0[((c >> 4) << 10) + (f << 4) + (c & 15)];
        }
    }
    __syncthreads();

    // ================= layer 0 =================
    inorm(sm, tid);
    gemmW_ep(sm, tid, 0);   // internal sync; hp16 -> H_, scores -> SV_/DV_
    __syncthreads();

    { // mask DV, per-warp d-max
        int n = tid & 63;
        float d = sm[DV_ + tid];
        float dm = (sm[MSK_ + n] > 0.f) ? d : -3.0e38f;
        sm[DV_ + tid] = dm;
        float md = dm;
        #pragma unroll
        for (int off = 16; off > 0; off >>= 1)
            md = fmaxf(md, __shfl_xor_sync(0xffffffffu, md, off));
        if (lane == 0) sm[DMX_ + (tid >> 5)] = md;
    }
    __syncthreads();

    { // p-pass L0: thread = (head, row); MUFU exp; fp16 p stores; INVP = 512/psum
        int hh = tid >> 6, n = tid & 63;
        float sB = sm[SV_ + tid];
        float valid = sm[MSK_ + n];
        float dmx = fmaxf(sm[DMX_ + (hh << 1)], sm[DMX_ + (hh << 1) + 1]);
        float mxv = sB + dmx; mxv = fmaxf(mxv, 0.2f * mxv);
        float nml = -mxv * L2E;
        float psum = 0.f;
        unsigned* pb = smu + RG_ + hh * PHW + (n << 5);
        int nx = n & 15;
        const float* dvb = &sm[DV_ + (hh << 6)];
        #pragma unroll 4
        for (int c = 0; c < 16; c++) {
            float4 d4 = *(const float4*)&dvb[c << 2];
            float v, lr;
            float4 pv;
            v = sB + d4.x; lr = fmaxf(v, 0.2f * v); pv.x = ex2_(fmaf(lr, L2E, nml));
            v = sB + d4.y; lr = fmaxf(v, 0.2f * v); pv.y = ex2_(fmaf(lr, L2E, nml));
            v = sB + d4.z; lr = fmaxf(v, 0.2f * v); pv.z = ex2_(fmaf(lr, L2E, nml));
            v = sB + d4.w; lr = fmaxf(v, 0.2f * v); pv.w = ex2_(fmaf(lr, L2E, nml));
            if (valid <= 0.f) { pv.x = 1.f; pv.y = 1.f; pv.z = 1.f; pv.w = 1.f; }
            psum += (pv.x + pv.y) + (pv.z + pv.w);
            uint2 uu; uu.x = pk2(pv.x, pv.y); uu.y = pk2(pv.z, pv.w);
            *(uint2*)(pb + ((c ^ nx) << 1)) = uu;
        }
        sm[INVP_ + hh * 68 + n] = 512.0f / psum;
    }
    __syncthreads();

    aggregate(sm, smu, tid, 0, (float*)0);   // internal sync; ELU(out0)+b0 -> H_
    __syncthreads();

    // load W1 (overwrites dead p region)
    #pragma unroll
    for (int k = 0; k < 16; k++) {
        int i = tid + (k << 8);
        sm[RG_ + i] = w1[i];
    }
    __syncthreads();

    // ================= layer 1 =================
    inorm(sm, tid);
    gemmW_ep(sm, tid, 1);   // internal sync; hp16 -> H_, score partials -> RED_
    __syncthreads();

    if (tid < 64) { // combine partials, mask, DMX
        float s = sm[RED_ + tid] + sm[RED_ + 64 + tid];
        float d = sm[RED_ + 128 + tid] + sm[RED_ + 192 + tid];
        sm[SV_ + tid] = s;
        float dm = (sm[MSK_ + tid] > 0.f) ? d : -3.0e38f;
        sm[DV_ + tid] = dm;
        float md = dm;
        #pragma unroll
        for (int off = 16; off > 0; off >>= 1)
            md = fmaxf(md, __shfl_xor_sync(0xffffffffu, md, off));
        if (lane == 0) sm[DMX_ + 8 + (tid >> 5)] = md;
    }
    __syncthreads();

    { // p-pass L1: thread = (row, 16-m segment); fp16 p stores
        int row = tid & 63, seg = tid >> 6;
        float sB = sm[SV_ + row];
        float valid = sm[MSK_ + row];
        float dmx = fmaxf(sm[DMX_ + 8], sm[DMX_ + 9]);
        float mxv = sB + dmx; mxv = fmaxf(mxv, 0.2f * mxv);
        float nml = -mxv * L2E;
        float psum = 0.f;
        unsigned* pb = smu + RG_ + (row << 5);
        int nx = row & 12;
        #pragma unroll
        for (int i = 0; i < 4; i++) {
            int jj = (i + row) & 3;
            int sg = (seg << 2) + jj;
            float4 d4 = *(const float4*)&sm[DV_ + (sg << 2)];
            float v, lr;
            float4 pv;
            v = sB + d4.x; lr = fmaxf(v, 0.2f * v); pv.x = ex2_(fmaf(lr, L2E, nml));
            v = sB + d4.y; lr = fmaxf(v, 0.2f * v); pv.y = ex2_(fmaf(lr, L2E, nml));
            v = sB + d4.z; lr = fmaxf(v, 0.2f * v); pv.z = ex2_(fmaf(lr, L2E, nml));
            v = sB + d4.w; lr = fmaxf(v, 0.2f * v); pv.w = ex2_(fmaf(lr, L2E, nml));
            if (valid <= 0.f) { pv.x = 1.f; pv.y = 1.f; pv.z = 1.f; pv.w = 1.f; }
            psum += (pv.x + pv.y) + (pv.z + pv.w);
            uint2 uu; uu.x = pk2(pv.x, pv.y); uu.y = pk2(pv.z, pv.w);
            *(uint2*)(pb + (((sg ^ nx) & 15) << 1)) = uu;
        }
        sm[RED_ + tid] = psum;
    }
    __syncthreads();
    if (tid < 64)
        sm[INVP_ + tid] = 512.0f / (sm[RED_ + tid] + sm[RED_ + 64 + tid] +
                                    sm[RED_ + 128 + tid] + sm[RED_ + 192 + tid]);
    __syncthreads();

    aggregate(sm, smu, tid, 1, out + (size_t)b * 4096);
}

extern "C" void kernel_launch(void* const* d_in, const int* in_sizes, int n_in,
                              void* d_out, int out_size) {
    const float* x   = (const float*)d_in[0];
    const int*   fhi = (const int*)d_in[1];
    const float* w0  = (const float*)d_in[2];
    const float* as0 = (const float*)d_in[3];
    const float* ad0 = (const float*)d_in[4];
    const float* b0  = (const float*)d_in[5];
    const float* w1  = (const float*)d_in[6];
    const float* as1 = (const float*)d_in[7];
    const float* ad1 = (const float*)d_in[8];
    const float* b1  = (const float*)d_in[9];
    float* out = (float*)d_out;

    const int smem = SMW * 4;   // 56704 bytes
    cudaFuncSetAttribute(gat_kernel, cudaFuncAttributeMaxDynamicSharedMemorySize, smem);
    gat_kernel<<<8192, 256, smem>>>(x, fhi, w0, as0, ad0, b0, w1, as1, ad1, b1, out);
}